// round 8
// baseline (speedup 1.0000x reference)
#include <cuda_runtime.h>
#include <cuda_bf16.h>

#define S_GRID 7
#define CH 30
#define TILE 1470          // 7*7*30 floats per image
#define MAXM 16
#define NUMC 20
#define IPB 8              // images per block
#define NV4 2940           // float4s per block slice (IPB*TILE/4)
#define MAXPART 2048       // >= B/IPB

__device__ float g_partial[MAXPART];
__device__ unsigned int g_count = 0;

__device__ __forceinline__ float iou_fn(float a0, float a1, float a2, float a3,
                                        float b0, float b1, float b2, float b3) {
    float ax1 = a0 - a2 * 0.5f, ay1 = a1 - a3 * 0.5f;
    float ax2 = a0 + a2 * 0.5f, ay2 = a1 + a3 * 0.5f;
    float bx1 = b0 - b2 * 0.5f, by1 = b1 - b3 * 0.5f;
    float bx2 = b0 + b2 * 0.5f, by2 = b1 + b3 * 0.5f;
    float iw = fmaxf(fminf(ax2, bx2) - fmaxf(ax1, bx1), 0.0f);
    float ih = fmaxf(fminf(ay2, by2) - fmaxf(ay1, by1), 0.0f);
    float inter = iw * ih;
    float uni = a2 * a3 + b2 * b3 - inter;
    return inter / (uni + 1e-6f);
}

__device__ __forceinline__ float block_reduce_128(float v, float* s_red, int t) {
    #pragma unroll
    for (int off = 16; off > 0; off >>= 1)
        v += __shfl_down_sync(0xffffffffu, v, off);
    if ((t & 31) == 0) s_red[t >> 5] = v;
    __syncthreads();
    return s_red[0] + s_red[1] + s_red[2] + s_red[3];
}

__global__ __launch_bounds__(128, 10) void yolo_loss_stream2(
    const float* __restrict__ pred,
    const float* __restrict__ gt_xywh,
    const int*   __restrict__ gt_class,
    float* __restrict__ out,
    int nblk, int Btot) {

    const int t = threadIdx.x;
    const long long b0 = (long long)blockIdx.x * IPB;

    __shared__ int s_cell[IPB][MAXM];
    __shared__ float s_red[4];
    __shared__ int s_last;

    // ---- gt metadata: one box per thread (8 imgs x 16 boxes), coalesced ----
    float4 g = reinterpret_cast<const float4*>(gt_xywh)[(long long)blockIdx.x * 128 + t];
    int cls  = gt_class[(long long)blockIdx.x * 128 + t];
    const int img = t >> 4;        // 0..7
    const int m   = t & 15;        // 0..15
    // Faithful to reference: row from x, col from y.
    int row = min(max((int)floorf(g.x * 7.0f), 0), S_GRID - 1);
    int col = min(max((int)floorf(g.y * 7.0f), 0), S_GRID - 1);
    int cell = row * S_GRID + col;
    s_cell[img][m] = cell;
    __syncthreads();

    // first-occurrence-per-cell dedup (kept threads enumerate distinct object cells)
    int keep = 1;
    for (int i = 0; i < m; i++)
        if (s_cell[img][i] == cell) keep = 0;

    float acc = 0.0f;

    // ---- Phase 1: coalesced full stream of this block's 8-image pred slice.
    //      Confidence channels appear exactly at i4 mod 15 in {1,2,8,9}
    //      (lane 0,1,2,3 respectively); valid globally since 1470 % 30 == 0
    //      and NV4 % 15 == 0 keeps per-block phase = local index.
    {
        const float4* sp = reinterpret_cast<const float4*>(pred) + (long long)blockIdx.x * NV4;
        int p = t % 15;
        float ssum = 0.0f;
        #pragma unroll
        for (int k = 0; k < 23; k++) {
            int i4 = t + 128 * k;
            if (i4 < NV4) {
                float4 v = __ldg(&sp[i4]);
                float x = (p == 1) ? v.x : (p == 2) ? v.y :
                          (p == 8) ? v.z : (p == 9) ? v.w : 0.0f;
                ssum += x * x;
            }
            p += 8; if (p >= 15) p -= 15;
        }
        acc += 0.5f * ssum;            // LAMBDA_NOOBJ * sum over ALL cells
    }

    // ---- Phase 2: per-box terms; also subtract conf^2 at object cells ----
    if (keep) {
        float tx = g.x * 7.0f - (float)col;      // faithful x/y swap
        float ty = g.y * 7.0f - (float)row;
        float tw = sqrtf(g.z);
        float th = sqrtf(g.w);
        const float2* rp = reinterpret_cast<const float2*>(
            &pred[(b0 + img) * TILE + cell * CH]);   // 8B-aligned row

        float2 v0 = __ldg(&rp[0]);   // ch0,1
        float2 v1 = __ldg(&rp[1]);   // ch2,3
        float2 v2 = __ldg(&rp[2]);   // ch4,5
        float2 v3 = __ldg(&rp[3]);   // ch6,7
        float2 v4 = __ldg(&rp[4]);   // ch8,9

        // remove this object cell's contribution to the all-cells conf sum
        acc -= 0.5f * (v2.x * v2.x + v4.y * v4.y);

        float i1 = iou_fn(v0.x, v0.y, v1.x, v1.y, tx, ty, tw, th);
        float i2 = iou_fn(v2.y, v3.x, v3.y, v4.x, tx, ty, tw, th);
        bool use2 = (i2 >= i1);
        float bx = use2 ? v2.y : v0.x;
        float by = use2 ? v3.x : v0.y;
        float bw = use2 ? v3.y : v1.x;
        float bh = use2 ? v4.x : v1.y;
        float sc = use2 ? v4.y : v2.x;
        float si = use2 ? i2   : i1;

        float d0 = bx - tx, d1 = by - ty, d2 = bw - tw, d3 = bh - th;
        acc += 5.0f * (d0 * d0 + d1 * d1 + d2 * d2 + d3 * d3);  // LAMBDA_COORD
        float dc = sc - si;
        acc += dc * dc;

        // classes: channels 10..29, streamed as float2
        #pragma unroll
        for (int i = 0; i < 10; i++) {
            float2 v = __ldg(&rp[5 + i]);
            float e0 = v.x - ((2 * i     == cls) ? 1.0f : 0.0f);
            float e1 = v.y - ((2 * i + 1 == cls) ? 1.0f : 0.0f);
            acc += e0 * e0 + e1 * e1;
        }
    }

    // ---- block partial ----
    float tot = block_reduce_128(acc, s_red, t);
    if (t == 0) g_partial[blockIdx.x] = tot;

    // ---- fused final reduction: last block finishes ----
    __threadfence();
    if (t == 0) {
        unsigned int ticket = atomicAdd(&g_count, 1u);
        s_last = (ticket == (unsigned int)(nblk - 1));
    }
    __syncthreads();
    if (s_last) {
        __threadfence();
        float s = 0.0f;
        for (int i = t; i < nblk; i += 128)
            s += __ldcg(&g_partial[i]);
        __syncthreads();          // s_red reuse
        float fin = block_reduce_128(s, s_red, t);
        if (t == 0) {
            out[0] = fin / (float)Btot;
            g_count = 0;          // ready for next (replay) launch
        }
    }
}

extern "C" void kernel_launch(void* const* d_in, const int* in_sizes, int n_in,
                              void* d_out, int out_size) {
    const float* pred    = (const float*)d_in[0];
    const float* gt_xywh = (const float*)d_in[1];
    const int*   gt_cls  = (const int*)d_in[2];
    float* out = (float*)d_out;

    int B = in_sizes[0] / TILE;     // 16384
    int nblk = B / IPB;             // 2048

    yolo_loss_stream2<<<nblk, 128>>>(pred, gt_xywh, gt_cls, out, nblk, B);
}

// round 9
// speedup vs baseline: 1.9358x; 1.9358x over previous
#include <cuda_runtime.h>
#include <cuda_bf16.h>

#define S_GRID 7
#define CH 30
#define TILE 1470          // 7*7*30
#define MAXM 16
#define NUMC 20
#define IPB 8              // images per block
#define MAXPART 2048       // >= B/IPB

__device__ float g_partial[MAXPART];
__device__ unsigned int g_count = 0;

__device__ __forceinline__ float iou_fn(float a0, float a1, float a2, float a3,
                                        float b0, float b1, float b2, float b3) {
    float ax1 = a0 - a2 * 0.5f, ay1 = a1 - a3 * 0.5f;
    float ax2 = a0 + a2 * 0.5f, ay2 = a1 + a3 * 0.5f;
    float bx1 = b0 - b2 * 0.5f, by1 = b1 - b3 * 0.5f;
    float bx2 = b0 + b2 * 0.5f, by2 = b1 + b3 * 0.5f;
    float iw = fmaxf(fminf(ax2, bx2) - fmaxf(ax1, bx1), 0.0f);
    float ih = fmaxf(fminf(ay2, by2) - fmaxf(ay1, by1), 0.0f);
    float inter = iw * ih;
    float uni = a2 * a3 + b2 * b3 - inter;
    return inter / (uni + 1e-6f);
}

__device__ __forceinline__ float block_reduce_128(float v, float* s_red, int t) {
    #pragma unroll
    for (int off = 16; off > 0; off >>= 1)
        v += __shfl_down_sync(0xffffffffu, v, off);
    if ((t & 31) == 0) s_red[t >> 5] = v;
    __syncthreads();
    return s_red[0] + s_red[1] + s_red[2] + s_red[3];
}

__global__ __launch_bounds__(128) void yolo_loss_fused(
    const float* __restrict__ pred,
    const float* __restrict__ gt_xywh,
    const int*   __restrict__ gt_class,
    float* __restrict__ out,
    int nblk, int Btot) {

    const int t = threadIdx.x;
    const long long b0 = (long long)blockIdx.x * IPB;

    __shared__ int s_cell[IPB][MAXM];
    __shared__ float s_red[4];
    __shared__ int s_last;

    // ---- gt metadata: one box per thread (8 imgs x 16 boxes), coalesced ----
    float4 g = reinterpret_cast<const float4*>(gt_xywh)[(long long)blockIdx.x * 128 + t];
    int cls  = gt_class[(long long)blockIdx.x * 128 + t];
    const int img = t >> 4;        // 0..7
    const int m   = t & 15;        // 0..15
    // Faithful to reference: row from x, col from y.
    int row = min(max((int)floorf(g.x * 7.0f), 0), S_GRID - 1);
    int col = min(max((int)floorf(g.y * 7.0f), 0), S_GRID - 1);
    int cell = row * S_GRID + col;
    s_cell[img][m] = cell;
    __syncthreads();

    // first-occurrence-per-cell dedup: kept threads enumerate exactly the
    // distinct object cells of their image.
    int keep = 1;
    for (int i = 0; i < m; i++)
        if (s_cell[img][i] == cell) keep = 0;

    const float* base = pred + b0 * TILE;

    // ---- issue ALL loads first (maximize front-batched MLP) ----

    // noobj slots: 8 imgs x 98 (cell,ch) = 784, thread t owns idx = t + 128k.
    // k<6 always valid; k=6 valid only for t<16. NO masks: weight is always
    // 0.5; object-cell contributions are subtracted by kept-box threads below.
    float nv[6];
    #pragma unroll
    for (int k = 0; k < 6; k++) {
        int idx = t + 128 * k;
        int i  = idx / 98;
        int r  = idx - i * 98;
        nv[k] = __ldg(base + i * TILE + (r >> 1) * CH + ((r & 1) ? 9 : 4));
    }
    float nv6 = 0.0f;
    if (t < 16) {
        int idx = t + 768;
        int i  = idx / 98;
        int r  = idx - i * 98;
        nv6 = __ldg(base + i * TILE + (r >> 1) * CH + ((r & 1) ? 9 : 4));
    }

    // box row loads (only kept threads)
    float2 v0, v1, v2, v3, v4, vc[10];
    if (keep) {
        const float2* rp = reinterpret_cast<const float2*>(
            base + img * TILE + cell * CH);          // 8B-aligned row
        v0 = __ldg(&rp[0]);   // ch0,1
        v1 = __ldg(&rp[1]);   // ch2,3
        v2 = __ldg(&rp[2]);   // ch4,5
        v3 = __ldg(&rp[3]);   // ch6,7
        v4 = __ldg(&rp[4]);   // ch8,9
        #pragma unroll
        for (int i = 0; i < 10; i++)
            vc[i] = __ldg(&rp[5 + i]);               // ch10..29
    }

    // ---- consume ----
    float acc = 0.0f;

    float ssum = nv6 * nv6;
    #pragma unroll
    for (int k = 0; k < 6; k++)
        ssum += nv[k] * nv[k];
    acc += 0.5f * ssum;                              // LAMBDA_NOOBJ * all slots

    if (keep) {
        // subtract this distinct object cell's conf^2 from the all-slots sum
        acc -= 0.5f * (v2.x * v2.x + v4.y * v4.y);

        float tx = g.x * 7.0f - (float)col;          // faithful x/y swap
        float ty = g.y * 7.0f - (float)row;
        float tw = sqrtf(g.z);
        float th = sqrtf(g.w);

        float i1 = iou_fn(v0.x, v0.y, v1.x, v1.y, tx, ty, tw, th);
        float i2 = iou_fn(v2.y, v3.x, v3.y, v4.x, tx, ty, tw, th);
        bool use2 = (i2 >= i1);
        float bx = use2 ? v2.y : v0.x;
        float by = use2 ? v3.x : v0.y;
        float bw = use2 ? v3.y : v1.x;
        float bh = use2 ? v4.x : v1.y;
        float sc = use2 ? v4.y : v2.x;
        float si = use2 ? i2   : i1;

        float d0 = bx - tx, d1 = by - ty, d2 = bw - tw, d3 = bh - th;
        acc += 5.0f * (d0 * d0 + d1 * d1 + d2 * d2 + d3 * d3);  // LAMBDA_COORD
        float dc = sc - si;
        acc += dc * dc;

        #pragma unroll
        for (int i = 0; i < 10; i++) {
            float e0 = vc[i].x - ((2 * i     == cls) ? 1.0f : 0.0f);
            float e1 = vc[i].y - ((2 * i + 1 == cls) ? 1.0f : 0.0f);
            acc += e0 * e0 + e1 * e1;
        }
    }

    // ---- block partial ----
    float tot = block_reduce_128(acc, s_red, t);
    if (t == 0) g_partial[blockIdx.x] = tot;

    // ---- fused final reduction: last block finishes ----
    __threadfence();
    if (t == 0) {
        unsigned int ticket = atomicAdd(&g_count, 1u);
        s_last = (ticket == (unsigned int)(nblk - 1));
    }
    __syncthreads();
    if (s_last) {
        __threadfence();
        float s = 0.0f;
        for (int i = t; i < nblk; i += 128)
            s += __ldcg(&g_partial[i]);
        __syncthreads();          // s_red reuse
        float fin = block_reduce_128(s, s_red, t);
        if (t == 0) {
            out[0] = fin / (float)Btot;
            g_count = 0;          // ready for next (replay) launch
        }
    }
}

extern "C" void kernel_launch(void* const* d_in, const int* in_sizes, int n_in,
                              void* d_out, int out_size) {
    const float* pred    = (const float*)d_in[0];
    const float* gt_xywh = (const float*)d_in[1];
    const int*   gt_cls  = (const int*)d_in[2];
    float* out = (float*)d_out;

    int B = in_sizes[0] / TILE;     // 16384
    int nblk = B / IPB;             // 2048

    yolo_loss_fused<<<nblk, 128>>>(pred, gt_xywh, gt_cls, out, nblk, B);
}